// round 7
// baseline (speedup 1.0000x reference)
#include <cuda_runtime.h>

// GCNRegressor: 3-layer GCN, N=100000 nodes, E=1.6M edges, D=128.
// Strategy:
//   1. Build symmetric-normalized CSR (by dst) once per launch (no fp atomics
//      in the hot path; aggregation becomes a pull-style gather).
//   2. fp32 register-tiled GEMM for the two 128x128 layers.
//   3. Warp-per-node aggregation (float4 per lane), bias+ReLU fused.
//   4. Layer-2 aggregation fused with the final GEMV (W3) -> h3 scalar per node.
//   5. Scalar aggregation for layer 3 -> relu -> d_out.

#define D     128
#define NMAX  100096
#define EMAX  1600512

static __device__ float g_deg[NMAX];
static __device__ float g_dis[NMAX];
static __device__ int   g_cnt[NMAX];
static __device__ int   g_rowptr[NMAX + 1];
static __device__ int   g_woff[NMAX];
static __device__ int   g_esrc[EMAX];
static __device__ float g_enorm[EMAX];
static __device__ __align__(16) float g_h[(size_t)NMAX * D];
static __device__ __align__(16) float g_a[(size_t)NMAX * D];
static __device__ float g_h3[NMAX];
static __device__ int   g_part[256];

// ---------------------------------------------------------------------------
// Preprocessing: degree, rsqrt, counts, scan, scatter into CSR
// ---------------------------------------------------------------------------

__global__ void k_init(int n) {
    int i = blockIdx.x * blockDim.x + threadIdx.x;
    if (i < n) { g_deg[i] = 1.0f; g_cnt[i] = 0; }   // self-loop weight 1
}

__global__ void k_degcnt(const int* __restrict__ dst, const float* __restrict__ w, int e) {
    int i = blockIdx.x * blockDim.x + threadIdx.x;
    if (i < e) {
        int d = dst[i];
        atomicAdd(&g_deg[d], w[i]);
        atomicAdd(&g_cnt[d], 1);
    }
}

__global__ void k_dis(int n) {
    int i = blockIdx.x * blockDim.x + threadIdx.x;
    if (i < n) g_dis[i] = rsqrtf(g_deg[i]);         // deg >= 1 always (self-loop)
}

// Block-level exclusive scan of g_cnt -> g_rowptr (local), block sums -> g_part
__global__ void k_scan1(int n) {
    __shared__ int sh[1024];
    int t = threadIdx.x;
    int i = blockIdx.x * 1024 + t;
    int v = (i < n) ? g_cnt[i] : 0;
    sh[t] = v;
    __syncthreads();
    for (int off = 1; off < 1024; off <<= 1) {
        int add = (t >= off) ? sh[t - off] : 0;
        __syncthreads();
        sh[t] += add;
        __syncthreads();
    }
    if (i < n) g_rowptr[i] = sh[t] - v;             // exclusive within block
    if (t == 1023) g_part[blockIdx.x] = sh[1023];
}

__global__ void k_scan2(int nb) {
    if (blockIdx.x == 0 && threadIdx.x == 0) {
        int run = 0;
        for (int b = 0; b < nb; b++) { int t = g_part[b]; g_part[b] = run; run += t; }
    }
}

__global__ void k_scan3(int n, int e) {
    int i = blockIdx.x * blockDim.x + threadIdx.x;
    if (i < n) {
        int v = g_rowptr[i] + g_part[i >> 10];
        g_rowptr[i] = v;
        g_woff[i] = v;
    }
    if (i == 0) g_rowptr[n] = e;
}

__global__ void k_scatter(const int* __restrict__ src, const int* __restrict__ dst,
                          const float* __restrict__ w, int e) {
    int i = blockIdx.x * blockDim.x + threadIdx.x;
    if (i >= e) return;
    int s = src[i], d = dst[i];
    int pos = atomicAdd(&g_woff[d], 1);
    g_esrc[pos] = s;
    g_enorm[pos] = g_dis[s] * w[i] * g_dis[d];
}

// ---------------------------------------------------------------------------
// GEMM: C[n,128] = X[n,128] @ W[128,128]   (fp32, BM=64 x BN=128 per block)
// 256 threads, each computes an 8x4 micro-tile.
// ---------------------------------------------------------------------------

#define BM 64
#define BK 16

__global__ void k_gemm(const float* __restrict__ X, const float* __restrict__ W,
                       float* __restrict__ C, int n) {
    __shared__ float As[BK][BM];     // k-major
    __shared__ float Bs[BK][D];
    int tid = threadIdx.x;
    int m_blk = blockIdx.x * BM;
    int tn  = tid & 31;              // col group (4 cols)
    int tmg = tid >> 5;              // row group (8 rows)

    float acc[8][4];
#pragma unroll
    for (int i = 0; i < 8; i++)
#pragma unroll
        for (int j = 0; j < 4; j++) acc[i][j] = 0.0f;

    for (int k0 = 0; k0 < D; k0 += BK) {
        // Load A tile (64x16) transposed into As[k][m]
        {
            int r  = tid >> 2;               // row 0..63
            int kq = (tid & 3) * 4;          // k sub 0,4,8,12
            int gm = m_blk + r;
            float4 v = make_float4(0.f, 0.f, 0.f, 0.f);
            if (gm < n) v = *(const float4*)&X[(size_t)gm * D + k0 + kq];
            As[kq + 0][r] = v.x;
            As[kq + 1][r] = v.y;
            As[kq + 2][r] = v.z;
            As[kq + 3][r] = v.w;
        }
        // Load B tile (16x128)
#pragma unroll
        for (int j = 0; j < 2; j++) {
            int idx = tid + j * 256;         // 0..511 float4 slots
            int r = idx >> 5;                // 0..15
            int c = (idx & 31) * 4;
            *(float4*)&Bs[r][c] = *(const float4*)&W[(k0 + r) * D + c];
        }
        __syncthreads();

#pragma unroll
        for (int kk = 0; kk < BK; kk++) {
            float4 a0 = *(const float4*)&As[kk][tmg * 8];
            float4 a1 = *(const float4*)&As[kk][tmg * 8 + 4];
            float4 bv = *(const float4*)&Bs[kk][tn * 4];
            float a[8] = {a0.x, a0.y, a0.z, a0.w, a1.x, a1.y, a1.z, a1.w};
            float b[4] = {bv.x, bv.y, bv.z, bv.w};
#pragma unroll
            for (int i = 0; i < 8; i++)
#pragma unroll
                for (int j = 0; j < 4; j++) acc[i][j] = fmaf(a[i], b[j], acc[i][j]);
        }
        __syncthreads();
    }

#pragma unroll
    for (int i = 0; i < 8; i++) {
        int gm = m_blk + tmg * 8 + i;
        if (gm < n) {
            *(float4*)&C[(size_t)gm * D + tn * 4] =
                make_float4(acc[i][0], acc[i][1], acc[i][2], acc[i][3]);
        }
    }
}

// ---------------------------------------------------------------------------
// Aggregation: warp per node, lane owns 4 dims. out = relu(sum + b)
// ---------------------------------------------------------------------------

__global__ void k_agg_relu(const float* __restrict__ h, const float* __restrict__ bias,
                           float* __restrict__ o, int n) {
    int gw = (blockIdx.x * blockDim.x + threadIdx.x) >> 5;
    if (gw >= n) return;
    int lane = threadIdx.x & 31;
    const float4* hp = (const float4*)h;

    float dis = g_dis[gw];
    float self = dis * dis;
    float4 hv = hp[(size_t)gw * 32 + lane];
    float ax = self * hv.x, ay = self * hv.y, az = self * hv.z, aw = self * hv.w;

    int beg = g_rowptr[gw], end = g_rowptr[gw + 1];
    for (int t = beg; t < end; t++) {
        int s = g_esrc[t];
        float w = g_enorm[t];
        float4 v = hp[(size_t)s * 32 + lane];
        ax = fmaf(w, v.x, ax); ay = fmaf(w, v.y, ay);
        az = fmaf(w, v.z, az); aw = fmaf(w, v.w, aw);
    }
    float4 b = ((const float4*)bias)[lane];
    ax = fmaxf(ax + b.x, 0.f); ay = fmaxf(ay + b.y, 0.f);
    az = fmaxf(az + b.z, 0.f); aw = fmaxf(aw + b.w, 0.f);
    ((float4*)o)[(size_t)gw * 32 + lane] = make_float4(ax, ay, az, aw);
}

// Layer-2 aggregation fused with the final GEMV: h3 = relu(agg(h)+b2) . W3
__global__ void k_agg_relu_gemv(const float* __restrict__ h, const float* __restrict__ bias,
                                const float* __restrict__ W3, float* __restrict__ h3, int n) {
    int gw = (blockIdx.x * blockDim.x + threadIdx.x) >> 5;
    if (gw >= n) return;
    int lane = threadIdx.x & 31;
    const float4* hp = (const float4*)h;

    float dis = g_dis[gw];
    float self = dis * dis;
    float4 hv = hp[(size_t)gw * 32 + lane];
    float ax = self * hv.x, ay = self * hv.y, az = self * hv.z, aw = self * hv.w;

    int beg = g_rowptr[gw], end = g_rowptr[gw + 1];
    for (int t = beg; t < end; t++) {
        int s = g_esrc[t];
        float w = g_enorm[t];
        float4 v = hp[(size_t)s * 32 + lane];
        ax = fmaf(w, v.x, ax); ay = fmaf(w, v.y, ay);
        az = fmaf(w, v.z, az); aw = fmaf(w, v.w, aw);
    }
    float4 b = ((const float4*)bias)[lane];
    ax = fmaxf(ax + b.x, 0.f); ay = fmaxf(ay + b.y, 0.f);
    az = fmaxf(az + b.z, 0.f); aw = fmaxf(aw + b.w, 0.f);

    float4 w3 = __ldg(&((const float4*)W3)[lane]);
    float s = ax * w3.x + ay * w3.y + az * w3.z + aw * w3.w;
#pragma unroll
    for (int off = 16; off; off >>= 1) s += __shfl_xor_sync(0xFFFFFFFFu, s, off);
    if (lane == 0) h3[gw] = s;
}

// Layer-3 scalar aggregation: out = relu(agg(h3) + b3)
__global__ void k_agg3(const float* __restrict__ h3, const float* __restrict__ b3,
                       float* __restrict__ out, int n) {
    int i = blockIdx.x * blockDim.x + threadIdx.x;
    if (i >= n) return;
    float dis = g_dis[i];
    float acc = dis * dis * h3[i];
    int beg = g_rowptr[i], end = g_rowptr[i + 1];
    for (int t = beg; t < end; t++)
        acc = fmaf(g_enorm[t], h3[g_esrc[t]], acc);
    acc += b3[0];
    out[i] = fmaxf(acc, 0.f);
}

// ---------------------------------------------------------------------------
// Launch
// ---------------------------------------------------------------------------

static inline int cdiv(int a, int b) { return (a + b - 1) / b; }

extern "C" void kernel_launch(void* const* d_in, const int* in_sizes, int n_in,
                              void* d_out, int out_size) {
    const float* x  = (const float*)d_in[0];
    const int*   ei = (const int*)d_in[1];
    const float* ew = (const float*)d_in[2];
    const float* W1 = (const float*)d_in[3];
    const float* b1 = (const float*)d_in[4];
    const float* W2 = (const float*)d_in[5];
    const float* b2 = (const float*)d_in[6];
    const float* W3 = (const float*)d_in[7];
    const float* b3 = (const float*)d_in[8];
    float* out = (float*)d_out;

    int n = in_sizes[0] / D;
    int e = in_sizes[1] / 2;
    const int* src = ei;
    const int* dst = ei + e;

    float *hbuf, *abuf, *h3buf;
    cudaGetSymbolAddress((void**)&hbuf, g_h);
    cudaGetSymbolAddress((void**)&abuf, g_a);
    cudaGetSymbolAddress((void**)&h3buf, g_h3);

    int nb1024 = cdiv(n, 1024);

    // --- Build normalized CSR (by dst) ---
    k_init<<<cdiv(n, 256), 256>>>(n);
    k_degcnt<<<cdiv(e, 256), 256>>>(dst, ew, e);
    k_dis<<<cdiv(n, 256), 256>>>(n);
    k_scan1<<<nb1024, 1024>>>(n);
    k_scan2<<<1, 32>>>(nb1024);
    k_scan3<<<cdiv(n, 256), 256>>>(n, e);
    k_scatter<<<cdiv(e, 256), 256>>>(src, dst, ew, e);

    // --- Layer 1 ---
    k_gemm<<<cdiv(n, BM), 256>>>(x, W1, hbuf, n);
    k_agg_relu<<<cdiv(n * 32, 256), 256>>>(hbuf, b1, abuf, n);

    // --- Layer 2 (aggregation fused with final GEMV) ---
    k_gemm<<<cdiv(n, BM), 256>>>(abuf, W2, hbuf, n);
    k_agg_relu_gemv<<<cdiv(n * 32, 256), 256>>>(hbuf, b2, W3, h3buf, n);

    // --- Layer 3 (scalar) ---
    k_agg3<<<cdiv(n, 256), 256>>>(h3buf, b3, out, n);
}

// round 8
// speedup vs baseline: 1.3334x; 1.3334x over previous
#include <cuda_runtime.h>

// GCNRegressor: 3-layer GCN, N=100000, E=1.6M, D=128.
//   1. Build normalized CSR (by dst) once per launch.
//   2. FFMA2 (fma.rn.f32x2) register-tiled 128x128 GEMM, broadcast-only LDS.
//   3. Warp-per-node aggregation, 4-way unrolled gather (MLP=4), bias+ReLU fused.
//   4. Layer-2 aggregation fused with final GEMV (W3).

#define D     128
#define NMAX  100096
#define EMAX  1600512

static __device__ float g_deg[NMAX];
static __device__ float g_dis[NMAX];
static __device__ int   g_cnt[NMAX];
static __device__ int   g_rowptr[NMAX + 1];
static __device__ int   g_woff[NMAX];
static __device__ int   g_esrc[EMAX];
static __device__ float g_enorm[EMAX];
static __device__ __align__(16) float g_h[(size_t)NMAX * D];
static __device__ __align__(16) float g_a[(size_t)NMAX * D];
static __device__ float g_h3[NMAX];
static __device__ int   g_part[256];

// ---------------------------------------------------------------------------
// Packed f32x2 helpers (FFMA2 — only reachable via PTX)
// ---------------------------------------------------------------------------
#define PACK2(d, x, y)   asm("mov.b64 %0, {%1, %2};" : "=l"(d) : "f"(x), "f"(y))
#define DUP2(d, x)       asm("mov.b64 %0, {%1, %1};" : "=l"(d) : "f"(x))
#define FMA2(c, a, b)    asm("fma.rn.f32x2 %0, %1, %2, %0;" : "+l"(c) : "l"(a), "l"(b))
#define UNPACK2(x, y, d) asm("mov.b64 {%0, %1}, %2;" : "=f"(x), "=f"(y) : "l"(d))

// ---------------------------------------------------------------------------
// Preprocessing: degree, rsqrt, counts, scan, scatter into CSR
// ---------------------------------------------------------------------------

__global__ void k_init(int n) {
    int i = blockIdx.x * blockDim.x + threadIdx.x;
    if (i < n) { g_deg[i] = 1.0f; g_cnt[i] = 0; }   // self-loop weight 1
}

__global__ void k_degcnt(const int* __restrict__ dst, const float* __restrict__ w, int e) {
    int i = blockIdx.x * blockDim.x + threadIdx.x;
    if (i < e) {
        int d = dst[i];
        atomicAdd(&g_deg[d], w[i]);
        atomicAdd(&g_cnt[d], 1);
    }
}

__global__ void k_dis(int n) {
    int i = blockIdx.x * blockDim.x + threadIdx.x;
    if (i < n) g_dis[i] = rsqrtf(g_deg[i]);
}

__global__ void k_scan1(int n) {
    __shared__ int sh[1024];
    int t = threadIdx.x;
    int i = blockIdx.x * 1024 + t;
    int v = (i < n) ? g_cnt[i] : 0;
    sh[t] = v;
    __syncthreads();
    for (int off = 1; off < 1024; off <<= 1) {
        int add = (t >= off) ? sh[t - off] : 0;
        __syncthreads();
        sh[t] += add;
        __syncthreads();
    }
    if (i < n) g_rowptr[i] = sh[t] - v;
    if (t == 1023) g_part[blockIdx.x] = sh[1023];
}

__global__ void k_scan2(int nb) {
    if (blockIdx.x == 0 && threadIdx.x == 0) {
        int run = 0;
        for (int b = 0; b < nb; b++) { int t = g_part[b]; g_part[b] = run; run += t; }
    }
}

__global__ void k_scan3(int n, int e) {
    int i = blockIdx.x * blockDim.x + threadIdx.x;
    if (i < n) {
        int v = g_rowptr[i] + g_part[i >> 10];
        g_rowptr[i] = v;
        g_woff[i] = v;
    }
    if (i == 0) g_rowptr[n] = e;
}

__global__ void k_scatter(const int* __restrict__ src, const int* __restrict__ dst,
                          const float* __restrict__ w, int e) {
    int i = blockIdx.x * blockDim.x + threadIdx.x;
    if (i >= e) return;
    int s = src[i], d = dst[i];
    int pos = atomicAdd(&g_woff[d], 1);
    g_esrc[pos] = s;
    g_enorm[pos] = g_dis[s] * w[i] * g_dis[d];
}

// ---------------------------------------------------------------------------
// GEMM: C[n,128] = X[n,128] @ W[128,128]
// Block tile 128x128, 256 threads, 8x8 micro-tile per thread, FFMA2 math.
// As is k-major (transposed) with XOR row-block swizzle -> conflict-free STS,
// and all inner-loop LDS are warp-broadcast float4s (conflict-free).
// ---------------------------------------------------------------------------

#define BM  128
#define BKG 16

__global__ void __launch_bounds__(256)
k_gemm(const float* __restrict__ X, const float* __restrict__ W,
       float* __restrict__ C, int n, int guard) {
    __shared__ float As[BKG][BM + 4];   // row stride 132 words
    __shared__ float Bs[BKG][D];
    int tid = threadIdx.x;
    int m_blk = blockIdx.x * BM;
    int col8 = (tid & 15) * 8;
    int g    = tid >> 4;                 // row-block 0..15
    int row8 = g * 8;

    unsigned long long acc[8][4];
#pragma unroll
    for (int i = 0; i < 8; i++)
#pragma unroll
        for (int j = 0; j < 4; j++) acc[i][j] = 0ULL;

    for (int k0 = 0; k0 < D; k0 += BKG) {
        // --- A tile 128x16, stored transposed with swizzle ---
#pragma unroll
        for (int j = 0; j < 2; j++) {
            int idx = tid + j * 256;         // 0..511
            int rl  = idx & 7;
            int kq4 = (idx >> 3) & 3;        // which float4 of the 16-k slice
            int rh  = idx >> 5;              // 0..15
            int r   = rh * 8 + rl;
            int gm  = m_blk + r;
            float4 v = make_float4(0.f, 0.f, 0.f, 0.f);
            if (!guard || gm < n) v = *(const float4*)&X[(size_t)gm * D + k0 + kq4 * 4];
            int rs = ((rh ^ kq4) * 8) + rl;  // swizzled store row
            As[kq4 * 4 + 0][rs] = v.x;
            As[kq4 * 4 + 1][rs] = v.y;
            As[kq4 * 4 + 2][rs] = v.z;
            As[kq4 * 4 + 3][rs] = v.w;
        }
        // --- B tile 16x128 ---
#pragma unroll
        for (int j = 0; j < 2; j++) {
            int idx = tid + j * 256;
            int r = idx >> 5;                // 0..15
            int c = (idx & 31) * 4;
            *(float4*)&Bs[r][c] = *(const float4*)&W[(k0 + r) * D + c];
        }
        __syncthreads();

#pragma unroll
        for (int kk = 0; kk < BKG; kk++) {
            int ab = (g ^ (kk >> 2)) * 8;    // de-swizzled row-block
            float4 a0 = *(const float4*)&As[kk][ab];
            float4 a1 = *(const float4*)&As[kk][ab + 4];
            float4 b0 = *(const float4*)&Bs[kk][col8];
            float4 b1 = *(const float4*)&Bs[kk][col8 + 4];

            unsigned long long ap[8], bp[4];
            DUP2(ap[0], a0.x); DUP2(ap[1], a0.y); DUP2(ap[2], a0.z); DUP2(ap[3], a0.w);
            DUP2(ap[4], a1.x); DUP2(ap[5], a1.y); DUP2(ap[6], a1.z); DUP2(ap[7], a1.w);
            PACK2(bp[0], b0.x, b0.y); PACK2(bp[1], b0.z, b0.w);
            PACK2(bp[2], b1.x, b1.y); PACK2(bp[3], b1.z, b1.w);
#pragma unroll
            for (int i = 0; i < 8; i++)
#pragma unroll
                for (int j = 0; j < 4; j++) FMA2(acc[i][j], ap[i], bp[j]);
        }
        __syncthreads();
    }

    // Epilogue: C rows always < NMAX (internal buffers), no store guard needed.
#pragma unroll
    for (int i = 0; i < 8; i++) {
        int gm = m_blk + row8 + i;
        float o0, o1, o2, o3, o4, o5, o6, o7;
        UNPACK2(o0, o1, acc[i][0]); UNPACK2(o2, o3, acc[i][1]);
        UNPACK2(o4, o5, acc[i][2]); UNPACK2(o6, o7, acc[i][3]);
        *(float4*)&C[(size_t)gm * D + col8]     = make_float4(o0, o1, o2, o3);
        *(float4*)&C[(size_t)gm * D + col8 + 4] = make_float4(o4, o5, o6, o7);
    }
}

// ---------------------------------------------------------------------------
// Aggregation: warp per node, lane owns 4 dims, 4-way unrolled gather (MLP=4)
// ---------------------------------------------------------------------------

__global__ void k_agg_relu(const float* __restrict__ h, const float* __restrict__ bias,
                           float* __restrict__ o, int n) {
    int gw = (blockIdx.x * blockDim.x + threadIdx.x) >> 5;
    if (gw >= n) return;
    int lane = threadIdx.x & 31;
    const float4* hp = (const float4*)h;

    float dis = g_dis[gw];
    float self = dis * dis;
    float4 hv = hp[(size_t)gw * 32 + lane];
    float ax = self * hv.x, ay = self * hv.y, az = self * hv.z, aw = self * hv.w;

    int t = g_rowptr[gw], end = g_rowptr[gw + 1];
    for (; t + 4 <= end; t += 4) {
        int s0 = g_esrc[t], s1 = g_esrc[t + 1], s2 = g_esrc[t + 2], s3 = g_esrc[t + 3];
        float w0 = g_enorm[t], w1 = g_enorm[t + 1], w2 = g_enorm[t + 2], w3 = g_enorm[t + 3];
        float4 v0 = hp[(size_t)s0 * 32 + lane];
        float4 v1 = hp[(size_t)s1 * 32 + lane];
        float4 v2 = hp[(size_t)s2 * 32 + lane];
        float4 v3 = hp[(size_t)s3 * 32 + lane];
        ax = fmaf(w0, v0.x, ax); ay = fmaf(w0, v0.y, ay); az = fmaf(w0, v0.z, az); aw = fmaf(w0, v0.w, aw);
        ax = fmaf(w1, v1.x, ax); ay = fmaf(w1, v1.y, ay); az = fmaf(w1, v1.z, az); aw = fmaf(w1, v1.w, aw);
        ax = fmaf(w2, v2.x, ax); ay = fmaf(w2, v2.y, ay); az = fmaf(w2, v2.z, az); aw = fmaf(w2, v2.w, aw);
        ax = fmaf(w3, v3.x, ax); ay = fmaf(w3, v3.y, ay); az = fmaf(w3, v3.z, az); aw = fmaf(w3, v3.w, aw);
    }
    for (; t < end; t++) {
        int s = g_esrc[t];
        float w = g_enorm[t];
        float4 v = hp[(size_t)s * 32 + lane];
        ax = fmaf(w, v.x, ax); ay = fmaf(w, v.y, ay);
        az = fmaf(w, v.z, az); aw = fmaf(w, v.w, aw);
    }
    float4 b = ((const float4*)bias)[lane];
    ax = fmaxf(ax + b.x, 0.f); ay = fmaxf(ay + b.y, 0.f);
    az = fmaxf(az + b.z, 0.f); aw = fmaxf(aw + b.w, 0.f);
    ((float4*)o)[(size_t)gw * 32 + lane] = make_float4(ax, ay, az, aw);
}

// Layer-2 aggregation fused with the final GEMV: h3 = relu(agg(h)+b2) . W3
__global__ void k_agg_relu_gemv(const float* __restrict__ h, const float* __restrict__ bias,
                                const float* __restrict__ W3, float* __restrict__ h3, int n) {
    int gw = (blockIdx.x * blockDim.x + threadIdx.x) >> 5;
    if (gw >= n) return;
    int lane = threadIdx.x & 31;
    const float4* hp = (const float4*)h;

    float dis = g_dis[gw];
    float self = dis * dis;
    float4 hv = hp[(size_t)gw * 32 + lane];
    float ax = self * hv.x, ay = self * hv.y, az = self * hv.z, aw = self * hv.w;

    int t = g_rowptr[gw], end = g_rowptr[gw + 1];
    for (; t + 4 <= end; t += 4) {
        int s0 = g_esrc[t], s1 = g_esrc[t + 1], s2 = g_esrc[t + 2], s3 = g_esrc[t + 3];
        float w0 = g_enorm[t], w1 = g_enorm[t + 1], w2 = g_enorm[t + 2], w3 = g_enorm[t + 3];
        float4 v0 = hp[(size_t)s0 * 32 + lane];
        float4 v1 = hp[(size_t)s1 * 32 + lane];
        float4 v2 = hp[(size_t)s2 * 32 + lane];
        float4 v3 = hp[(size_t)s3 * 32 + lane];
        ax = fmaf(w0, v0.x, ax); ay = fmaf(w0, v0.y, ay); az = fmaf(w0, v0.z, az); aw = fmaf(w0, v0.w, aw);
        ax = fmaf(w1, v1.x, ax); ay = fmaf(w1, v1.y, ay); az = fmaf(w1, v1.z, az); aw = fmaf(w1, v1.w, aw);
        ax = fmaf(w2, v2.x, ax); ay = fmaf(w2, v2.y, ay); az = fmaf(w2, v2.z, az); aw = fmaf(w2, v2.w, aw);
        ax = fmaf(w3, v3.x, ax); ay = fmaf(w3, v3.y, ay); az = fmaf(w3, v3.z, az); aw = fmaf(w3, v3.w, aw);
    }
    for (; t < end; t++) {
        int s = g_esrc[t];
        float w = g_enorm[t];
        float4 v = hp[(size_t)s * 32 + lane];
        ax = fmaf(w, v.x, ax); ay = fmaf(w, v.y, ay);
        az = fmaf(w, v.z, az); aw = fmaf(w, v.w, aw);
    }
    float4 b = ((const float4*)bias)[lane];
    ax = fmaxf(ax + b.x, 0.f); ay = fmaxf(ay + b.y, 0.f);
    az = fmaxf(az + b.z, 0.f); aw = fmaxf(aw + b.w, 0.f);

    float4 w3v = __ldg(&((const float4*)W3)[lane]);
    float s = ax * w3v.x + ay * w3v.y + az * w3v.z + aw * w3v.w;
#pragma unroll
    for (int off = 16; off; off >>= 1) s += __shfl_xor_sync(0xFFFFFFFFu, s, off);
    if (lane == 0) h3[gw] = s;
}

// Layer-3 scalar aggregation: out = relu(agg(h3) + b3)
__global__ void k_agg3(const float* __restrict__ h3, const float* __restrict__ b3,
                       float* __restrict__ out, int n) {
    int i = blockIdx.x * blockDim.x + threadIdx.x;
    if (i >= n) return;
    float dis = g_dis[i];
    float acc = dis * dis * h3[i];
    int beg = g_rowptr[i], end = g_rowptr[i + 1];
    for (int t = beg; t < end; t++)
        acc = fmaf(g_enorm[t], h3[g_esrc[t]], acc);
    acc += b3[0];
    out[i] = fmaxf(acc, 0.f);
}

// ---------------------------------------------------------------------------
// Launch
// ---------------------------------------------------------------------------

static inline int cdiv(int a, int b) { return (a + b - 1) / b; }

extern "C" void kernel_launch(void* const* d_in, const int* in_sizes, int n_in,
                              void* d_out, int out_size) {
    const float* x  = (const float*)d_in[0];
    const int*   ei = (const int*)d_in[1];
    const float* ew = (const float*)d_in[2];
    const float* W1 = (const float*)d_in[3];
    const float* b1 = (const float*)d_in[4];
    const float* W2 = (const float*)d_in[5];
    const float* b2 = (const float*)d_in[6];
    const float* W3 = (const float*)d_in[7];
    const float* b3 = (const float*)d_in[8];
    float* out = (float*)d_out;

    int n = in_sizes[0] / D;
    int e = in_sizes[1] / 2;
    const int* src = ei;
    const int* dst = ei + e;

    float *hbuf, *abuf, *h3buf;
    cudaGetSymbolAddress((void**)&hbuf, g_h);
    cudaGetSymbolAddress((void**)&abuf, g_a);
    cudaGetSymbolAddress((void**)&h3buf, g_h3);

    int nb1024 = cdiv(n, 1024);

    // --- Build normalized CSR (by dst) ---
    k_init<<<cdiv(n, 256), 256>>>(n);
    k_degcnt<<<cdiv(e, 256), 256>>>(dst, ew, e);
    k_dis<<<cdiv(n, 256), 256>>>(n);
    k_scan1<<<nb1024, 1024>>>(n);
    k_scan2<<<1, 32>>>(nb1024);
    k_scan3<<<cdiv(n, 256), 256>>>(n, e);
    k_scatter<<<cdiv(e, 256), 256>>>(src, dst, ew, e);

    // --- Layer 1 ---
    k_gemm<<<cdiv(n, BM), 256>>>(x, W1, hbuf, n, 1);       // guard: x has exactly n rows
    k_agg_relu<<<cdiv(n * 32, 256), 256>>>(hbuf, b1, abuf, n);

    // --- Layer 2 (aggregation fused with final GEMV) ---
    k_gemm<<<cdiv(n, BM), 256>>>(abuf, W2, hbuf, n, 0);    // abuf padded to NMAX rows
    k_agg_relu_gemv<<<cdiv(n * 32, 256), 256>>>(hbuf, b2, W3, h3buf, n);

    // --- Layer 3 (scalar) ---
    k_agg3<<<cdiv(n, 256), 256>>>(h3buf, b3, out, n);
}

// round 9
// speedup vs baseline: 1.5287x; 1.1465x over previous
#include <cuda_runtime.h>
#include <cuda_fp16.h>

// GCNRegressor: 3-layer GCN, N=100000, E=1.6M, D=128.
//   1. Build normalized CSR (by dst) once per launch; edges packed int2{src,norm}.
//   2. FFMA2 (fma.rn.f32x2) register-tiled 128x128 GEMM, fp32 in, fp16 out.
//   3. Warp-per-node aggregation over fp16 h-table (half the L2 gather traffic),
//      fp32 accumulate, bias+ReLU fused.
//   4. Layer-2 aggregation fused with final GEMV (W3).

#define D     128
#define NMAX  100096
#define EMAX  1600512

static __device__ float g_deg[NMAX];
static __device__ float g_dis[NMAX];
static __device__ int   g_cnt[NMAX];
static __device__ int   g_rowptr[NMAX + 1];
static __device__ int   g_woff[NMAX];
static __device__ __align__(16) int2   g_edge[EMAX];           // {src, norm as bits}
static __device__ __align__(16) __half g_h[(size_t)NMAX * D];  // fp16 gather table
static __device__ __align__(16) float  g_a[(size_t)NMAX * D];  // fp32 agg output
static __device__ float g_h3[NMAX];
static __device__ int   g_part[256];

// ---------------------------------------------------------------------------
// Packed f32x2 helpers (FFMA2 — only reachable via PTX)
// ---------------------------------------------------------------------------
#define PACK2(d, x, y)   asm("mov.b64 %0, {%1, %2};" : "=l"(d) : "f"(x), "f"(y))
#define DUP2(d, x)       asm("mov.b64 %0, {%1, %1};" : "=l"(d) : "f"(x))
#define FMA2(c, a, b)    asm("fma.rn.f32x2 %0, %1, %2, %0;" : "+l"(c) : "l"(a), "l"(b))
#define UNPACK2(x, y, d) asm("mov.b64 {%0, %1}, %2;" : "=f"(x), "=f"(y) : "l"(d))

// ---------------------------------------------------------------------------
// Preprocessing: degree, rsqrt, counts, scan, scatter into CSR
// ---------------------------------------------------------------------------

__global__ void k_init(int n) {
    int i = blockIdx.x * blockDim.x + threadIdx.x;
    if (i < n) { g_deg[i] = 1.0f; g_cnt[i] = 0; }   // self-loop weight 1
}

__global__ void k_degcnt(const int* __restrict__ dst, const float* __restrict__ w, int e) {
    int i = blockIdx.x * blockDim.x + threadIdx.x;
    if (i < e) {
        int d = dst[i];
        atomicAdd(&g_deg[d], w[i]);
        atomicAdd(&g_cnt[d], 1);
    }
}

__global__ void k_dis(int n) {
    int i = blockIdx.x * blockDim.x + threadIdx.x;
    if (i < n) g_dis[i] = rsqrtf(g_deg[i]);
}

__global__ void k_scan1(int n) {
    __shared__ int sh[1024];
    int t = threadIdx.x;
    int i = blockIdx.x * 1024 + t;
    int v = (i < n) ? g_cnt[i] : 0;
    sh[t] = v;
    __syncthreads();
    for (int off = 1; off < 1024; off <<= 1) {
        int add = (t >= off) ? sh[t - off] : 0;
        __syncthreads();
        sh[t] += add;
        __syncthreads();
    }
    if (i < n) g_rowptr[i] = sh[t] - v;
    if (t == 1023) g_part[blockIdx.x] = sh[1023];
}

__global__ void k_scan2(int nb) {
    if (blockIdx.x == 0 && threadIdx.x == 0) {
        int run = 0;
        for (int b = 0; b < nb; b++) { int t = g_part[b]; g_part[b] = run; run += t; }
    }
}

__global__ void k_scan3(int n, int e) {
    int i = blockIdx.x * blockDim.x + threadIdx.x;
    if (i < n) {
        int v = g_rowptr[i] + g_part[i >> 10];
        g_rowptr[i] = v;
        g_woff[i] = v;
    }
    if (i == 0) g_rowptr[n] = e;
}

__global__ void k_scatter(const int* __restrict__ src, const int* __restrict__ dst,
                          const float* __restrict__ w, int e) {
    int i = blockIdx.x * blockDim.x + threadIdx.x;
    if (i >= e) return;
    int s = src[i], d = dst[i];
    int pos = atomicAdd(&g_woff[d], 1);
    float nrm = g_dis[s] * w[i] * g_dis[d];
    g_edge[pos] = make_int2(s, __float_as_int(nrm));
}

// ---------------------------------------------------------------------------
// GEMM: C16[n,128] = X[n,128] @ W[128,128], fp32 math (FFMA2), fp16 output.
// Block tile 128x128, 256 threads, 8x8 micro-tile per thread.
// As is k-major (transposed) with XOR row-block swizzle -> conflict-free STS;
// all inner-loop LDS are warp-broadcast float4s (conflict-free).
// ---------------------------------------------------------------------------

#define BM  128
#define BKG 16

__global__ void __launch_bounds__(256)
k_gemm(const float* __restrict__ X, const float* __restrict__ W,
       __half* __restrict__ C, int n, int guard) {
    __shared__ float As[BKG][BM + 4];   // row stride 132 words
    __shared__ float Bs[BKG][D];
    int tid = threadIdx.x;
    int m_blk = blockIdx.x * BM;
    int col8 = (tid & 15) * 8;
    int g    = tid >> 4;                 // row-block 0..15
    int row8 = g * 8;

    unsigned long long acc[8][4];
#pragma unroll
    for (int i = 0; i < 8; i++)
#pragma unroll
        for (int j = 0; j < 4; j++) acc[i][j] = 0ULL;

    for (int k0 = 0; k0 < D; k0 += BKG) {
        // --- A tile 128x16, stored transposed with swizzle ---
#pragma unroll
        for (int j = 0; j < 2; j++) {
            int idx = tid + j * 256;         // 0..511
            int rl  = idx & 7;
            int kq4 = (idx >> 3) & 3;        // which float4 of the 16-k slice
            int rh  = idx >> 5;              // 0..15
            int r   = rh * 8 + rl;
            int gm  = m_blk + r;
            float4 v = make_float4(0.f, 0.f, 0.f, 0.f);
            if (!guard || gm < n) v = *(const float4*)&X[(size_t)gm * D + k0 + kq4 * 4];
            int rs = ((rh ^ kq4) * 8) + rl;  // swizzled store row
            As[kq4 * 4 + 0][rs] = v.x;
            As[kq4 * 4 + 1][rs] = v.y;
            As[kq4 * 4 + 2][rs] = v.z;
            As[kq4 * 4 + 3][rs] = v.w;
        }
        // --- B tile 16x128 ---
#pragma unroll
        for (int j = 0; j < 2; j++) {
            int idx = tid + j * 256;
            int r = idx >> 5;                // 0..15
            int c = (idx & 31) * 4;
            *(float4*)&Bs[r][c] = *(const float4*)&W[(k0 + r) * D + c];
        }
        __syncthreads();

#pragma unroll
        for (int kk = 0; kk < BKG; kk++) {
            int ab = (g ^ (kk >> 2)) * 8;    // de-swizzled row-block
            float4 a0 = *(const float4*)&As[kk][ab];
            float4 a1 = *(const float4*)&As[kk][ab + 4];
            float4 b0 = *(const float4*)&Bs[kk][col8];
            float4 b1 = *(const float4*)&Bs[kk][col8 + 4];

            unsigned long long ap[8], bp[4];
            DUP2(ap[0], a0.x); DUP2(ap[1], a0.y); DUP2(ap[2], a0.z); DUP2(ap[3], a0.w);
            DUP2(ap[4], a1.x); DUP2(ap[5], a1.y); DUP2(ap[6], a1.z); DUP2(ap[7], a1.w);
            PACK2(bp[0], b0.x, b0.y); PACK2(bp[1], b0.z, b0.w);
            PACK2(bp[2], b1.x, b1.y); PACK2(bp[3], b1.z, b1.w);
#pragma unroll
            for (int i = 0; i < 8; i++)
#pragma unroll
                for (int j = 0; j < 4; j++) FMA2(acc[i][j], ap[i], bp[j]);
        }
        __syncthreads();
    }

    // Epilogue: convert to fp16, one 16B store per row. C rows < NMAX always.
#pragma unroll
    for (int i = 0; i < 8; i++) {
        int gm = m_blk + row8 + i;
        float o0, o1, o2, o3, o4, o5, o6, o7;
        UNPACK2(o0, o1, acc[i][0]); UNPACK2(o2, o3, acc[i][1]);
        UNPACK2(o4, o5, acc[i][2]); UNPACK2(o6, o7, acc[i][3]);
        __half2 p0 = __floats2half2_rn(o0, o1);
        __half2 p1 = __floats2half2_rn(o2, o3);
        __half2 p2 = __floats2half2_rn(o4, o5);
        __half2 p3 = __floats2half2_rn(o6, o7);
        uint4 st;
        st.x = *(unsigned*)&p0; st.y = *(unsigned*)&p1;
        st.z = *(unsigned*)&p2; st.w = *(unsigned*)&p3;
        *(uint4*)&C[(size_t)gm * D + col8] = st;
    }
}

// ---------------------------------------------------------------------------
// Aggregation: warp per node, lane owns 4 dims (uint2 = 4 halves per gather),
// 4-way unrolled gather (MLP=4), fp32 accumulate, bias+ReLU fused.
// ---------------------------------------------------------------------------

__device__ __forceinline__ void h4_fma(float w, uint2 u,
                                       float& ax, float& ay, float& az, float& aw) {
    __half2 h01 = *(__half2*)&u.x;
    __half2 h23 = *(__half2*)&u.y;
    float2 f01 = __half22float2(h01);
    float2 f23 = __half22float2(h23);
    ax = fmaf(w, f01.x, ax); ay = fmaf(w, f01.y, ay);
    az = fmaf(w, f23.x, az); aw = fmaf(w, f23.y, aw);
}

__global__ void k_agg_relu(const __half* __restrict__ h, const float* __restrict__ bias,
                           float* __restrict__ o, int n) {
    int gw = (blockIdx.x * blockDim.x + threadIdx.x) >> 5;
    if (gw >= n) return;
    int lane = threadIdx.x & 31;
    const uint2* hp = (const uint2*)h;       // 32 uint2 per row

    float dis = g_dis[gw];
    float self = dis * dis;
    float ax = 0.f, ay = 0.f, az = 0.f, aw = 0.f;
    h4_fma(self, hp[(size_t)gw * 32 + lane], ax, ay, az, aw);

    int t = g_rowptr[gw], end = g_rowptr[gw + 1];
    for (; t + 4 <= end; t += 4) {
        int2 e0 = g_edge[t],     e1 = g_edge[t + 1];
        int2 e2 = g_edge[t + 2], e3 = g_edge[t + 3];
        uint2 v0 = hp[(size_t)e0.x * 32 + lane];
        uint2 v1 = hp[(size_t)e1.x * 32 + lane];
        uint2 v2 = hp[(size_t)e2.x * 32 + lane];
        uint2 v3 = hp[(size_t)e3.x * 32 + lane];
        h4_fma(__int_as_float(e0.y), v0, ax, ay, az, aw);
        h4_fma(__int_as_float(e1.y), v1, ax, ay, az, aw);
        h4_fma(__int_as_float(e2.y), v2, ax, ay, az, aw);
        h4_fma(__int_as_float(e3.y), v3, ax, ay, az, aw);
    }
    for (; t < end; t++) {
        int2 e = g_edge[t];
        h4_fma(__int_as_float(e.y), hp[(size_t)e.x * 32 + lane], ax, ay, az, aw);
    }
    float4 b = ((const float4*)bias)[lane];
    ax = fmaxf(ax + b.x, 0.f); ay = fmaxf(ay + b.y, 0.f);
    az = fmaxf(az + b.z, 0.f); aw = fmaxf(aw + b.w, 0.f);
    ((float4*)o)[(size_t)gw * 32 + lane] = make_float4(ax, ay, az, aw);
}

// Layer-2 aggregation fused with the final GEMV: h3 = relu(agg(h)+b2) . W3
__global__ void k_agg_relu_gemv(const __half* __restrict__ h, const float* __restrict__ bias,
                                const float* __restrict__ W3, float* __restrict__ h3, int n) {
    int gw = (blockIdx.x * blockDim.x + threadIdx.x) >> 5;
    if (gw >= n) return;
    int lane = threadIdx.x & 31;
    const uint2* hp = (const uint2*)h;

    float dis = g_dis[gw];
    float self = dis * dis;
    float ax = 0.f, ay = 0.f, az = 0.f, aw = 0.f;
    h4_fma(self, hp[(size_t)gw * 32 + lane], ax, ay, az, aw);

    int t = g_rowptr[gw], end = g_rowptr[gw + 1];
    for (; t + 4 <= end; t += 4) {
        int2 e0 = g_edge[t],     e1 = g_edge[t + 1];
        int2 e2 = g_edge[t + 2], e3 = g_edge[t + 3];
        uint2 v0 = hp[(size_t)e0.x * 32 + lane];
        uint2 v1 = hp[(size_t)e1.x * 32 + lane];
        uint2 v2 = hp[(size_t)e2.x * 32 + lane];
        uint2 v3 = hp[(size_t)e3.x * 32 + lane];
        h4_fma(__int_as_float(e0.y), v0, ax, ay, az, aw);
        h4_fma(__int_as_float(e1.y), v1, ax, ay, az, aw);
        h4_fma(__int_as_float(e2.y), v2, ax, ay, az, aw);
        h4_fma(__int_as_float(e3.y), v3, ax, ay, az, aw);
    }
    for (; t < end; t++) {
        int2 e = g_edge[t];
        h4_fma(__int_as_float(e.y), hp[(size_t)e.x * 32 + lane], ax, ay, az, aw);
    }
    float4 b = ((const float4*)bias)[lane];
    ax = fmaxf(ax + b.x, 0.f); ay = fmaxf(ay + b.y, 0.f);
    az = fmaxf(az + b.z, 0.f); aw = fmaxf(aw + b.w, 0.f);

    float4 w3v = __ldg(&((const float4*)W3)[lane]);
    float s = ax * w3v.x + ay * w3v.y + az * w3v.z + aw * w3v.w;
#pragma unroll
    for (int off = 16; off; off >>= 1) s += __shfl_xor_sync(0xFFFFFFFFu, s, off);
    if (lane == 0) h3[gw] = s;
}

// Layer-3 scalar aggregation: out = relu(agg(h3) + b3)
__global__ void k_agg3(const float* __restrict__ h3, const float* __restrict__ b3,
                       float* __restrict__ out, int n) {
    int i = blockIdx.x * blockDim.x + threadIdx.x;
    if (i >= n) return;
    float dis = g_dis[i];
    float acc = dis * dis * h3[i];
    int beg = g_rowptr[i], end = g_rowptr[i + 1];
    for (int t = beg; t < end; t++) {
        int2 e = g_edge[t];
        acc = fmaf(__int_as_float(e.y), h3[e.x], acc);
    }
    acc += b3[0];
    out[i] = fmaxf(acc, 0.f);
}

// ---------------------------------------------------------------------------
// Launch
// ---------------------------------------------------------------------------

static inline int cdiv(int a, int b) { return (a + b - 1) / b; }

extern "C" void kernel_launch(void* const* d_in, const int* in_sizes, int n_in,
                              void* d_out, int out_size) {
    const float* x  = (const float*)d_in[0];
    const int*   ei = (const int*)d_in[1];
    const float* ew = (const float*)d_in[2];
    const float* W1 = (const float*)d_in[3];
    const float* b1 = (const float*)d_in[4];
    const float* W2 = (const float*)d_in[5];
    const float* b2 = (const float*)d_in[6];
    const float* W3 = (const float*)d_in[7];
    const float* b3 = (const float*)d_in[8];
    float* out = (float*)d_out;

    int n = in_sizes[0] / D;
    int e = in_sizes[1] / 2;
    const int* src = ei;
    const int* dst = ei + e;

    __half* hbuf;
    float *abuf, *h3buf;
    cudaGetSymbolAddress((void**)&hbuf, g_h);
    cudaGetSymbolAddress((void**)&abuf, g_a);
    cudaGetSymbolAddress((void**)&h3buf, g_h3);

    int nb1024 = cdiv(n, 1024);

    // --- Build normalized CSR (by dst) ---
    k_init<<<cdiv(n, 256), 256>>>(n);
    k_degcnt<<<cdiv(e, 256), 256>>>(dst, ew, e);
    k_dis<<<cdiv(n, 256), 256>>>(n);
    k_scan1<<<nb1024, 1024>>>(n);
    k_scan2<<<1, 32>>>(nb1024);
    k_scan3<<<cdiv(n, 256), 256>>>(n, e);
    k_scatter<<<cdiv(e, 256), 256>>>(src, dst, ew, e);

    // --- Layer 1 ---
    k_gemm<<<cdiv(n, BM), 256>>>(x, W1, hbuf, n, 1);       // guard: x has exactly n rows
    k_agg_relu<<<cdiv(n * 32, 256), 256>>>(hbuf, b1, abuf, n);

    // --- Layer 2 (aggregation fused with final GEMV) ---
    k_gemm<<<cdiv(n, BM), 256>>>(abuf, W2, hbuf, n, 0);    // abuf padded to NMAX rows
    k_agg_relu_gemv<<<cdiv(n * 32, 256), 256>>>(hbuf, b2, W3, h3buf, n);

    // --- Layer 3 (scalar) ---
    k_agg3<<<cdiv(n, 256), 256>>>(h3buf, b3, out, n);
}

// round 11
// speedup vs baseline: 1.6387x; 1.0720x over previous
#include <cuda_runtime.h>
#include <cuda_fp16.h>

// GCNRegressor: 3-layer GCN, N=100000, E=1.6M, D=128.
//   1. CSR build (by dst) forked onto a second stream, overlapping GEMM1.
//   2. FFMA2 (fma.rn.f32x2) register-tiled 128x128 GEMM, fp32 in, fp16 out.
//   3. Warp-per-node aggregation over fp16 h-table, fp32 accumulate, bias+ReLU.
//   4. Layer-2 aggregation fused with final GEMV (W3).

#define D     128
#define NMAX  100096
#define EMAX  1600512

static __device__ float g_deg[NMAX];
static __device__ float g_dis[NMAX];
static __device__ int   g_cnt[NMAX];
static __device__ int   g_rowptr[NMAX + 1];
static __device__ int   g_woff[NMAX];
static __device__ __align__(16) int2   g_edge[EMAX];           // {src, norm as bits}
static __device__ __align__(16) __half g_h[(size_t)NMAX * D];  // fp16 gather table
static __device__ __align__(16) float  g_a[(size_t)NMAX * D];  // fp32 agg output
static __device__ float g_h3[NMAX];
static __device__ int   g_part[256];

// ---------------------------------------------------------------------------
// Packed f32x2 helpers (FFMA2 — only reachable via PTX)
// ---------------------------------------------------------------------------
#define DUP2(d, x)       asm("mov.b64 %0, {%1, %1};" : "=l"(d) : "f"(x))
#define FMA2(c, a, b)    asm("fma.rn.f32x2 %0, %1, %2, %0;" : "+l"(c) : "l"(a), "l"(b))
#define UNPACK2(x, y, d) asm("mov.b64 {%0, %1}, %2;" : "=f"(x), "=f"(y) : "l"(d))

// ---------------------------------------------------------------------------
// Preprocessing: degree, counts, scan(+rsqrt), scatter into CSR
// ---------------------------------------------------------------------------

__global__ void k_init(int n) {
    int i = blockIdx.x * blockDim.x + threadIdx.x;
    if (i < n) { g_deg[i] = 1.0f; g_cnt[i] = 0; }   // self-loop weight 1
}

__global__ void k_degcnt(const int* __restrict__ dst, const float* __restrict__ w, int e) {
    int i = blockIdx.x * blockDim.x + threadIdx.x;
    if (i < e) {
        int d = dst[i];
        atomicAdd(&g_deg[d], w[i]);
        atomicAdd(&g_cnt[d], 1);
    }
}

// Block-level exclusive scan of g_cnt; also computes g_dis = rsqrt(deg).
__global__ void k_scan1(int n) {
    __shared__ int sh[1024];
    int t = threadIdx.x;
    int i = blockIdx.x * 1024 + t;
    int v = (i < n) ? g_cnt[i] : 0;
    if (i < n) g_dis[i] = rsqrtf(g_deg[i]);
    sh[t] = v;
    __syncthreads();
    for (int off = 1; off < 1024; off <<= 1) {
        int add = (t >= off) ? sh[t - off] : 0;
        __syncthreads();
        sh[t] += add;
        __syncthreads();
    }
    if (i < n) g_rowptr[i] = sh[t] - v;
    if (t == 1023) g_part[blockIdx.x] = sh[1023];
}

__global__ void k_scan2(int nb) {
    if (blockIdx.x == 0 && threadIdx.x == 0) {
        int run = 0;
        for (int b = 0; b < nb; b++) { int t = g_part[b]; g_part[b] = run; run += t; }
    }
}

__global__ void k_scan3(int n, int e) {
    int i = blockIdx.x * blockDim.x + threadIdx.x;
    if (i < n) {
        int v = g_rowptr[i] + g_part[i >> 10];
        g_rowptr[i] = v;
        g_woff[i] = v;
    }
    if (i == 0) g_rowptr[n] = e;
}

__global__ void k_scatter(const int* __restrict__ src, const int* __restrict__ dst,
                          const float* __restrict__ w, int e) {
    int i = blockIdx.x * blockDim.x + threadIdx.x;
    if (i >= e) return;
    int s = src[i], d = dst[i];
    int pos = atomicAdd(&g_woff[d], 1);
    float nrm = g_dis[s] * w[i] * g_dis[d];
    g_edge[pos] = make_int2(s, __float_as_int(nrm));
}

// ---------------------------------------------------------------------------
// GEMM: C16[n,128] = X[n,128] @ W[128,128], fp32 math (FFMA2), fp16 output.
// Block tile 128x128, 256 threads, 8x8 micro-tile per thread.
// As k-major (transposed) with XOR row-block swizzle -> conflict-free STS;
// inner-loop LDS are warp-broadcast; B pairs loaded directly as u64 pairs.
// ---------------------------------------------------------------------------

#define BM  128
#define BKG 16

__global__ void __launch_bounds__(256)
k_gemm(const float* __restrict__ X, const float* __restrict__ W,
       __half* __restrict__ C, int n, int guard) {
    __shared__ __align__(16) float As[BKG][BM + 4];   // row stride 132 words
    __shared__ __align__(16) float Bs[BKG][D];
    int tid = threadIdx.x;
    int m_blk = blockIdx.x * BM;
    int col8 = (tid & 15) * 8;
    int g    = tid >> 4;                 // row-block 0..15
    int row8 = g * 8;

    unsigned long long acc[8][4];
#pragma unroll
    for (int i = 0; i < 8; i++)
#pragma unroll
        for (int j = 0; j < 4; j++) acc[i][j] = 0ULL;

    for (int k0 = 0; k0 < D; k0 += BKG) {
        // --- A tile 128x16, stored transposed with swizzle ---
#pragma unroll
        for (int j = 0; j < 2; j++) {
            int idx = tid + j * 256;         // 0..511
            int rl  = idx & 7;
            int kq4 = (idx >> 3) & 3;        // which float4 of the 16-k slice
            int rh  = idx >> 5;              // 0..15
            int r   = rh * 8 + rl;
            int gm  = m_blk + r;
            float4 v = make_float4(0.f, 0.f, 0.f, 0.f);
            if (!guard || gm < n) v = *(const float4*)&X[(size_t)gm * D + k0 + kq4 * 4];
            int rs = ((rh ^ kq4) * 8) + rl;  // swizzled store row
            As[kq4 * 4 + 0][rs] = v.x;
            As[kq4 * 4 + 1][rs] = v.y;
            As[kq4 * 4 + 2][rs] = v.z;
            As[kq4 * 4 + 3][rs] = v.w;
        }
        // --- B tile 16x128 ---
#pragma unroll
        for (int j = 0; j < 2; j++) {
            int idx = tid + j * 256;
            int r = idx >> 5;                // 0..15
            int c = (idx & 31) * 4;
            *(float4*)&Bs[r][c] = *(const float4*)&W[(k0 + r) * D + c];
        }
        __syncthreads();

#pragma unroll
        for (int kk = 0; kk < BKG; kk++) {
            int ab = (g ^ (kk >> 2)) * 8;    // de-swizzled row-block
            float4 a0 = *(const float4*)&As[kk][ab];
            float4 a1 = *(const float4*)&As[kk][ab + 4];
            // B pairs: bit-identical to packed f32x2 operands, no PACK movs.
            ulonglong2 bq0 = *(const ulonglong2*)&Bs[kk][col8];
            ulonglong2 bq1 = *(const ulonglong2*)&Bs[kk][col8 + 4];

            unsigned long long ap[8], bp[4];
            DUP2(ap[0], a0.x); DUP2(ap[1], a0.y); DUP2(ap[2], a0.z); DUP2(ap[3], a0.w);
            DUP2(ap[4], a1.x); DUP2(ap[5], a1.y); DUP2(ap[6], a1.z); DUP2(ap[7], a1.w);
            bp[0] = bq0.x; bp[1] = bq0.y; bp[2] = bq1.x; bp[3] = bq1.y;
#pragma unroll
            for (int i = 0; i < 8; i++)
#pragma unroll
                for (int j = 0; j < 4; j++) FMA2(acc[i][j], ap[i], bp[j]);
        }
        __syncthreads();
    }

    // Epilogue: convert to fp16, one 16B store per row. C rows < NMAX always.
#pragma unroll
    for (int i = 0; i < 8; i++) {
        int gm = m_blk + row8 + i;
        float o0, o1, o2, o3, o4, o5, o6, o7;
        UNPACK2(o0, o1, acc[i][0]); UNPACK2(o2, o3, acc[i][1]);
        UNPACK2(o4, o5, acc[i][2]); UNPACK2(o6, o7, acc[i][3]);
        __half2 p0 = __floats2half2_rn(o0, o1);
        __half2 p1 = __floats2half2_rn(o2, o3);
        __half2 p2 = __floats2half2_rn(o4, o5);
        __half2 p3 = __floats2half2_rn(o6, o7);
        uint4 st;
        st.x = *(unsigned*)&p0; st.y = *(unsigned*)&p1;
        st.z = *(unsigned*)&p2; st.w = *(unsigned*)&p3;
        *(uint4*)&C[(size_t)gm * D + col8] = st;
    }
}

// ---------------------------------------------------------------------------
// Aggregation: warp per node, lane owns 4 dims (uint2 = 4 halves per gather),
// 4-way unrolled gather (MLP=4), fp32 accumulate, bias+ReLU fused.
// ---------------------------------------------------------------------------

__device__ __forceinline__ void h4_fma(float w, uint2 u,
                                       float& ax, float& ay, float& az, float& aw) {
    __half2 h01 = *(__half2*)&u.x;
    __half2 h23 = *(__half2*)&u.y;
    float2 f01 = __half22float2(h01);
    float2 f23 = __half22float2(h23);
    ax = fmaf(w, f01.x, ax); ay = fmaf(w, f01.y, ay);
    az = fmaf(w, f23.x, az); aw = fmaf(w, f23.y, aw);
}

__global__ void k_agg_relu(const __half* __restrict__ h, const float* __restrict__ bias,
                           float* __restrict__ o, int n) {
    int gw = (blockIdx.x * blockDim.x + threadIdx.x) >> 5;
    if (gw >= n) return;
    int lane = threadIdx.x & 31;
    const uint2* hp = (const uint2*)h;       // 32 uint2 per row

    float dis = g_dis[gw];
    float self = dis * dis;
    float ax = 0.f, ay = 0.f, az = 0.f, aw = 0.f;
    h4_fma(self, hp[(size_t)gw * 32 + lane], ax, ay, az, aw);

    int t = g_rowptr[gw], end = g_rowptr[gw + 1];
    for (; t + 4 <= end; t += 4) {
        int2 e0 = g_edge[t],     e1 = g_edge[t + 1];
        int2 e2 = g_edge[t + 2], e3 = g_edge[t + 3];
        uint2 v0 = hp[(size_t)e0.x * 32 + lane];
        uint2 v1 = hp[(size_t)e1.x * 32 + lane];
        uint2 v2 = hp[(size_t)e2.x * 32 + lane];
        uint2 v3 = hp[(size_t)e3.x * 32 + lane];
        h4_fma(__int_as_float(e0.y), v0, ax, ay, az, aw);
        h4_fma(__int_as_float(e1.y), v1, ax, ay, az, aw);
        h4_fma(__int_as_float(e2.y), v2, ax, ay, az, aw);
        h4_fma(__int_as_float(e3.y), v3, ax, ay, az, aw);
    }
    for (; t < end; t++) {
        int2 e = g_edge[t];
        h4_fma(__int_as_float(e.y), hp[(size_t)e.x * 32 + lane], ax, ay, az, aw);
    }
    float4 b = ((const float4*)bias)[lane];
    ax = fmaxf(ax + b.x, 0.f); ay = fmaxf(ay + b.y, 0.f);
    az = fmaxf(az + b.z, 0.f); aw = fmaxf(aw + b.w, 0.f);
    ((float4*)o)[(size_t)gw * 32 + lane] = make_float4(ax, ay, az, aw);
}

// Layer-2 aggregation fused with the final GEMV: h3 = relu(agg(h)+b2) . W3
__global__ void k_agg_relu_gemv(const __half* __restrict__ h, const float* __restrict__ bias,
                                const float* __restrict__ W3, float* __restrict__ h3, int n) {
    int gw = (blockIdx.x * blockDim.x + threadIdx.x) >> 5;
    if (gw >= n) return;
    int lane = threadIdx.x & 31;
    const uint2* hp = (const uint2*)h;

    float dis = g_dis[gw];
    float self = dis * dis;
    float ax = 0.f, ay = 0.f, az = 0.f, aw = 0.f;
    h4_fma(self, hp[(size_t)gw * 32 + lane], ax, ay, az, aw);

    int t = g_rowptr[gw], end = g_rowptr[gw + 1];
    for (; t + 4 <= end; t += 4) {
        int2 e0 = g_edge[t],     e1 = g_edge[t + 1];
        int2 e2 = g_edge[t + 2], e3 = g_edge[t + 3];
        uint2 v0 = hp[(size_t)e0.x * 32 + lane];
        uint2 v1 = hp[(size_t)e1.x * 32 + lane];
        uint2 v2 = hp[(size_t)e2.x * 32 + lane];
        uint2 v3 = hp[(size_t)e3.x * 32 + lane];
        h4_fma(__int_as_float(e0.y), v0, ax, ay, az, aw);
        h4_fma(__int_as_float(e1.y), v1, ax, ay, az, aw);
        h4_fma(__int_as_float(e2.y), v2, ax, ay, az, aw);
        h4_fma(__int_as_float(e3.y), v3, ax, ay, az, aw);
    }
    for (; t < end; t++) {
        int2 e = g_edge[t];
        h4_fma(__int_as_float(e.y), hp[(size_t)e.x * 32 + lane], ax, ay, az, aw);
    }
    float4 b = ((const float4*)bias)[lane];
    ax = fmaxf(ax + b.x, 0.f); ay = fmaxf(ay + b.y, 0.f);
    az = fmaxf(az + b.z, 0.f); aw = fmaxf(aw + b.w, 0.f);

    float4 w3v = __ldg(&((const float4*)W3)[lane]);
    float s = ax * w3v.x + ay * w3v.y + az * w3v.z + aw * w3v.w;
#pragma unroll
    for (int off = 16; off; off >>= 1) s += __shfl_xor_sync(0xFFFFFFFFu, s, off);
    if (lane == 0) h3[gw] = s;
}

// Layer-3 scalar aggregation: out = relu(agg(h3) + b3)
__global__ void k_agg3(const float* __restrict__ h3, const float* __restrict__ b3,
                       float* __restrict__ out, int n) {
    int i = blockIdx.x * blockDim.x + threadIdx.x;
    if (i >= n) return;
    float dis = g_dis[i];
    float acc = dis * dis * h3[i];
    int beg = g_rowptr[i], end = g_rowptr[i + 1];
    for (int t = beg; t < end; t++) {
        int2 e = g_edge[t];
        acc = fmaf(__int_as_float(e.y), h3[e.x], acc);
    }
    acc += b3[0];
    out[i] = fmaxf(acc, 0.f);
}

// ---------------------------------------------------------------------------
// Launch: CSR build forked onto a second stream, overlapping GEMM1.
// Falls back to fully serial launches if stream/event creation failed.
// ---------------------------------------------------------------------------

static inline int cdiv(int a, int b) { return (a + b - 1) / b; }

extern "C" void kernel_launch(void* const* d_in, const int* in_sizes, int n_in,
                              void* d_out, int out_size) {
    const float* x  = (const float*)d_in[0];
    const int*   ei = (const int*)d_in[1];
    const float* ew = (const float*)d_in[2];
    const float* W1 = (const float*)d_in[3];
    const float* b1 = (const float*)d_in[4];
    const float* W2 = (const float*)d_in[5];
    const float* b2 = (const float*)d_in[6];
    const float* W3 = (const float*)d_in[7];
    const float* b3 = (const float*)d_in[8];
    float* out = (float*)d_out;

    int n = in_sizes[0] / D;
    int e = in_sizes[1] / 2;
    const int* src = ei;
    const int* dst = ei + e;

    __half* hbuf;
    float *abuf, *h3buf;
    cudaGetSymbolAddress((void**)&hbuf, g_h);
    cudaGetSymbolAddress((void**)&abuf, g_a);
    cudaGetSymbolAddress((void**)&h3buf, g_h3);

    // One-time stream/event creation (host-side resources only; no device mem).
    static cudaStream_t s_csr = nullptr;
    static cudaEvent_t ev_fork = nullptr, ev_join = nullptr;
    static int init_tried = 0;
    if (!init_tried) {
        init_tried = 1;
        if (cudaStreamCreateWithFlags(&s_csr, cudaStreamNonBlocking) != cudaSuccess) s_csr = nullptr;
        if (s_csr) {
            if (cudaEventCreateWithFlags(&ev_fork, cudaEventDisableTiming) != cudaSuccess ||
                cudaEventCreateWithFlags(&ev_join, cudaEventDisableTiming) != cudaSuccess) {
                s_csr = nullptr;   // fall back to serial
            }
        }
    }

    int nb1024 = cdiv(n, 1024);

    if (s_csr) {
        // --- Fork: CSR build on s_csr, GEMM1 on the main (capturing) stream ---
        cudaEventRecord(ev_fork, 0);
        cudaStreamWaitEvent(s_csr, ev_fork, 0);

        k_init   <<<cdiv(n, 256), 256, 0, s_csr>>>(n);
        k_degcnt <<<cdiv(e, 256), 256, 0, s_csr>>>(dst, ew, e);
        k_scan1  <<<nb1024, 1024, 0, s_csr>>>(n);          // also computes g_dis
        k_scan2  <<<1, 32, 0, s_csr>>>(nb1024);
        k_scan3  <<<cdiv(n, 256), 256, 0, s_csr>>>(n, e);
        k_scatter<<<cdiv(e, 256), 256, 0, s_csr>>>(src, dst, ew, e);
        cudaEventRecord(ev_join, s_csr);

        k_gemm<<<cdiv(n, BM), 256>>>(x, W1, hbuf, n, 1);   // overlaps CSR build

        // --- Join: aggregation needs both GEMM1 output and the CSR ---
        cudaStreamWaitEvent(0, ev_join, 0);
    } else {
        // Serial fallback (known-good ordering).
        k_init   <<<cdiv(n, 256), 256>>>(n);
        k_degcnt <<<cdiv(e, 256), 256>>>(dst, ew, e);
        k_scan1  <<<nb1024, 1024>>>(n);
        k_scan2  <<<1, 32>>>(nb1024);
        k_scan3  <<<cdiv(n, 256), 256>>>(n, e);
        k_scatter<<<cdiv(e, 256), 256>>>(src, dst, ew, e);
        k_gemm<<<cdiv(n, BM), 256>>>(x, W1, hbuf, n, 1);
    }

    // --- Layer 1 ---
    k_agg_relu<<<cdiv(n * 32, 256), 256>>>(hbuf, b1, abuf, n);

    // --- Layer 2 (aggregation fused with final GEMV) ---
    k_gemm<<<cdiv(n, BM), 256>>>(abuf, W2, hbuf, n, 0);   // abuf padded to NMAX rows
    k_agg_relu_gemv<<<cdiv(n * 32, 256), 256>>>(hbuf, b2, W3, h3buf, n);

    // --- Layer 3 (scalar) ---
    k_agg3<<<cdiv(n, 256), 256>>>(h3buf, b3, out, n);
}

// round 16
// speedup vs baseline: 1.6534x; 1.0090x over previous
#include <cuda_runtime.h>
#include <cuda_fp16.h>

// GCNRegressor: 3-layer GCN, N=100000, E=1.6M, D=128.
//   1. CSR build (by dst) forked onto a second stream, hidden under GEMM1.
//   2. FFMA2 (fma.rn.f32x2) register-tiled 128x128 GEMM, fp32 in, fp16 out.
//   3. Warp-per-node aggregation over fp16 tables, fp32 accumulate, bias+ReLU.
//   4. agg_relu(half B) overlaps GEMM2(half A) — legal now: GEMM2 writes g_h2
//      while agg reads g_h (separate tables; the R12 race is fixed).
//   5. Layer-2 aggregation fused with final GEMV (W3).

#define D     128
#define NMAX  100096
#define EMAX  1600512

static __device__ float g_deg[NMAX];
static __device__ float g_dis[NMAX];
static __device__ int   g_cnt[NMAX];
static __device__ int   g_rowptr[NMAX + 1];
static __device__ int   g_woff[NMAX];
static __device__ __align__(16) int2   g_edge[EMAX];            // {src, norm bits}
static __device__ __align__(16) __half g_h [(size_t)NMAX * D];  // layer-1 gather table
static __device__ __align__(16) __half g_h2[(size_t)NMAX * D];  // layer-2 gather table
static __device__ __align__(16) float  g_a [(size_t)NMAX * D];  // fp32 agg output
static __device__ float g_h3[NMAX];
static __device__ int   g_part[256];

// ---------------------------------------------------------------------------
// Packed f32x2 helpers (FFMA2 — only reachable via PTX)
// ---------------------------------------------------------------------------
#define DUP2(d, x)       asm("mov.b64 %0, {%1, %1};" : "=l"(d) : "f"(x))
#define FMA2(c, a, b)    asm("fma.rn.f32x2 %0, %1, %2, %0;" : "+l"(c) : "l"(a), "l"(b))
#define UNPACK2(x, y, d) asm("mov.b64 {%0, %1}, %2;" : "=f"(x), "=f"(y) : "l"(d))

// ---------------------------------------------------------------------------
// Preprocessing: degree+counts (arrays pre-zeroed by memset), scan, scatter
// ---------------------------------------------------------------------------

__global__ void k_degcnt(const int* __restrict__ dst, const float* __restrict__ w, int e) {
    int i = blockIdx.x * blockDim.x + threadIdx.x;
    if (i < e) {
        int d = dst[i];
        atomicAdd(&g_deg[d], w[i]);
        atomicAdd(&g_cnt[d], 1);
    }
}

// Block-level exclusive scan of g_cnt; also g_dis = rsqrt(deg + 1) (self-loop).
__global__ void k_scan1(int n) {
    __shared__ int sh[1024];
    int t = threadIdx.x;
    int i = blockIdx.x * 1024 + t;
    int v = (i < n) ? g_cnt[i] : 0;
    if (i < n) g_dis[i] = rsqrtf(g_deg[i] + 1.0f);
    sh[t] = v;
    __syncthreads();
    for (int off = 1; off < 1024; off <<= 1) {
        int add = (t >= off) ? sh[t - off] : 0;
        __syncthreads();
        sh[t] += add;
        __syncthreads();
    }
    if (i < n) g_rowptr[i] = sh[t] - v;
    if (t == 1023) g_part[blockIdx.x] = sh[1023];
}

// Warp-parallel exclusive scan of the block partials (nb <= 128).
__global__ void k_scan2(int nb) {
    int t = threadIdx.x;
    int per = (nb + 31) / 32;
    int beg = t * per;
    int s = 0;
    for (int j = 0; j < per; j++) {
        int idx = beg + j;
        if (idx < nb) s += g_part[idx];
    }
    int x = s;
    for (int off = 1; off < 32; off <<= 1) {
        int y = __shfl_up_sync(0xFFFFFFFFu, x, off);
        if (t >= off) x += y;
    }
    int run = x - s;          // exclusive prefix of this thread's chunk
    for (int j = 0; j < per; j++) {
        int idx = beg + j;
        if (idx < nb) {
            int v = g_part[idx];
            g_part[idx] = run;
            run += v;
        }
    }
}

__global__ void k_scan3(int n, int e) {
    int i = blockIdx.x * blockDim.x + threadIdx.x;
    if (i < n) {
        int v = g_rowptr[i] + g_part[i >> 10];
        g_rowptr[i] = v;
        g_woff[i] = v;
    }
    if (i == 0) g_rowptr[n] = e;
}

__global__ void k_scatter(const int* __restrict__ src, const int* __restrict__ dst,
                          const float* __restrict__ w, int e) {
    int i = blockIdx.x * blockDim.x + threadIdx.x;
    if (i >= e) return;
    int s = src[i], d = dst[i];
    int pos = atomicAdd(&g_woff[d], 1);
    float nrm = g_dis[s] * w[i] * g_dis[d];
    g_edge[pos] = make_int2(s, __float_as_int(nrm));
}

// ---------------------------------------------------------------------------
// GEMM: C16[rows,128] = X[rows,128] @ W[128,128], FFMA2 math, fp16 output.
// Block tile 128x128, 256 threads, 8x8 micro-tile; row_beg for chunking.
// ---------------------------------------------------------------------------

#define BM  128
#define BKG 16

__global__ void __launch_bounds__(256, 2)
k_gemm(const float* __restrict__ X, const float* __restrict__ W,
       __half* __restrict__ C, int n, int guard, int row_beg) {
    __shared__ __align__(16) float As[BKG][BM + 4];   // row stride 132 words
    __shared__ __align__(16) float Bs[BKG][D];
    int tid = threadIdx.x;
    int m_blk = row_beg + blockIdx.x * BM;
    int col8 = (tid & 15) * 8;
    int g    = tid >> 4;                 // row-block 0..15
    int row8 = g * 8;

    unsigned long long acc[8][4];
#pragma unroll
    for (int i = 0; i < 8; i++)
#pragma unroll
        for (int j = 0; j < 4; j++) acc[i][j] = 0ULL;

    for (int k0 = 0; k0 < D; k0 += BKG) {
        // --- A tile 128x16, stored transposed with swizzle ---
#pragma unroll
        for (int j = 0; j < 2; j++) {
            int idx = tid + j * 256;         // 0..511
            int rl  = idx & 7;
            int kq4 = (idx >> 3) & 3;        // which float4 of the 16-k slice
            int rh  = idx >> 5;              // 0..15
            int r   = rh * 8 + rl;
            int gm  = m_blk + r;
            float4 v = make_float4(0.f, 0.f, 0.f, 0.f);
            if (!guard || gm < n) v = *(const float4*)&X[(size_t)gm * D + k0 + kq4 * 4];
            int rs = ((rh ^ kq4) * 8) + rl;  // swizzled store row
            As[kq4 * 4 + 0][rs] = v.x;
            As[kq4 * 4 + 1][rs] = v.y;
            As[kq4 * 4 + 2][rs] = v.z;
            As[kq4 * 4 + 3][rs] = v.w;
        }
        // --- B tile 16x128 ---
#pragma unroll
        for (int j = 0; j < 2; j++) {
            int idx = tid + j * 256;
            int r = idx >> 5;                // 0..15
            int c = (idx & 31) * 4;
            *(float4*)&Bs[r][c] = *(const float4*)&W[(k0 + r) * D + c];
        }
        __syncthreads();

#pragma unroll
        for (int kk = 0; kk < BKG; kk++) {
            int ab = (g ^ (kk >> 2)) * 8;    // de-swizzled row-block
            float4 a0 = *(const float4*)&As[kk][ab];
            float4 a1 = *(const float4*)&As[kk][ab + 4];
            // B pairs: bit-identical to packed f32x2 operands, no PACK movs.
            ulonglong2 bq0 = *(const ulonglong2*)&Bs[kk][col8];
            ulonglong2 bq1 = *(const ulonglong2*)&Bs[kk][col8 + 4];

            unsigned long long ap[8], bp[4];
            DUP2(ap[0], a0.x); DUP2(ap[1], a0.y); DUP2(ap[2], a0.z); DUP2(ap[3], a0.w);
            DUP2(ap[4], a1.x); DUP2(ap[5], a1.y); DUP2(ap[6], a1.z); DUP2(ap[7], a1.w);
            bp[0] = bq0.x; bp[1] = bq0.y; bp[2] = bq1.x; bp[3] = bq1.y;
#pragma unroll
            for (int i = 0; i < 8; i++)
#pragma unroll
                for (int j = 0; j < 4; j++) FMA2(acc[i][j], ap[i], bp[j]);
        }
        __syncthreads();
    }

    // Epilogue: convert to fp16, one 16B store per row. C rows < NMAX always.
#pragma unroll
    for (int i = 0; i < 8; i++) {
        int gm = m_blk + row8 + i;
        float o0, o1, o2, o3, o4, o5, o6, o7;
        UNPACK2(o0, o1, acc[i][0]); UNPACK2(o2, o3, acc[i][1]);
        UNPACK2(o4, o5, acc[i][2]); UNPACK2(o6, o7, acc[i][3]);
        __half2 p0 = __floats2half2_rn(o0, o1);
        __half2 p1 = __floats2half2_rn(o2, o3);
        __half2 p2 = __floats2half2_rn(o4, o5);
        __half2 p3 = __floats2half2_rn(o6, o7);
        uint4 st;
        st.x = *(unsigned*)&p0; st.y = *(unsigned*)&p1;
        st.z = *(unsigned*)&p2; st.w = *(unsigned*)&p3;
        *(uint4*)&C[(size_t)gm * D + col8] = st;
    }
}

// ---------------------------------------------------------------------------
// Aggregation: warp per node, lane owns 4 dims (uint2 = 4 halves per gather),
// 4-way unrolled gather (MLP=4), fp32 accumulate, bias+ReLU fused.
// Node range [node_beg, node_end) for the producer-side chunk pipeline.
// ---------------------------------------------------------------------------

__device__ __forceinline__ void h4_fma(float w, uint2 u,
                                       float& ax, float& ay, float& az, float& aw) {
    __half2 h01 = *(__half2*)&u.x;
    __half2 h23 = *(__half2*)&u.y;
    float2 f01 = __half22float2(h01);
    float2 f23 = __half22float2(h23);
    ax = fmaf(w, f01.x, ax); ay = fmaf(w, f01.y, ay);
    az = fmaf(w, f23.x, az); aw = fmaf(w, f23.y, aw);
}

__global__ void k_agg_relu(const __half* __restrict__ h, const float* __restrict__ bias,
                           float* __restrict__ o, int node_beg, int node_end) {
    int gw = node_beg + ((blockIdx.x * blockDim.x + threadIdx.x) >> 5);
    if (gw >= node_end) return;
    int lane = threadIdx.x & 31;
    const uint2* hp = (const uint2*)h;       // 32 uint2 per row

    float dis = g_dis[gw];
    float self = dis * dis;
    float ax = 0.f, ay = 0.f, az = 0.f, aw = 0.f;
    h4_fma(self, hp[(size_t)gw * 32 + lane], ax, ay, az, aw);

    int t = g_rowptr[gw], end = g_rowptr[gw + 1];
    for (; t + 4 <= end; t += 4) {
        int2 e0 = g_edge[t],     e1 = g_edge[t + 1];
        int2 e2 = g_edge[t + 2], e3 = g_edge[t + 3];
        uint2 v0 = hp[(size_t)e0.x * 32 + lane];
        uint2 v1 = hp[(size_t)e1.x * 32 + lane];
        uint2 v2 = hp[(size_t)e2.x * 32 + lane];
        uint2 v3 = hp[(size_t)e3.x * 32 + lane];
        h4_fma(__int_as_float(e0.y), v0, ax, ay, az, aw);
        h4_fma(__int_as_float(e1.y), v1, ax, ay, az, aw);
        h4_fma(__int_as_float(e2.y), v2, ax, ay, az, aw);
        h4_fma(__int_as_float(e3.y), v3, ax, ay, az, aw);
    }
    for (; t < end; t++) {
        int2 e = g_edge[t];
        h4_fma(__int_as_float(e.y), hp[(size_t)e.x * 32 + lane], ax, ay, az, aw);
    }
    float4 b = ((const float4*)bias)[lane];
    ax = fmaxf(ax + b.x, 0.f); ay = fmaxf(ay + b.y, 0.f);
    az = fmaxf(az + b.z, 0.f); aw = fmaxf(aw + b.w, 0.f);
    ((float4*)o)[(size_t)gw * 32 + lane] = make_float4(ax, ay, az, aw);
}

// Layer-2 aggregation fused with the final GEMV: h3 = relu(agg(h)+b2) . W3
__global__ void k_agg_relu_gemv(const __half* __restrict__ h, const float* __restrict__ bias,
                                const float* __restrict__ W3, float* __restrict__ h3, int n) {
    int gw = (blockIdx.x * blockDim.x + threadIdx.x) >> 5;
    if (gw >= n) return;
    int lane = threadIdx.x & 31;
    const uint2* hp = (const uint2*)h;

    float dis = g_dis[gw];
    float self = dis * dis;
    float ax = 0.f, ay = 0.f, az = 0.f, aw = 0.f;
    h4_fma(self, hp[(size_t)gw * 32 + lane], ax, ay, az, aw);

    int t = g_rowptr[gw], end = g_rowptr[gw + 1];
    for (; t + 4 <= end; t += 4) {
        int2 e0 = g_edge[t],     e1 = g_edge[t + 1];
        int2 e2 = g_edge[t + 2], e3 = g_edge[t + 3];
        uint2 v0 = hp[(size_t)e0.x * 32 + lane];
        uint2 v1 = hp[(size_t)e1.x * 32 + lane];
        uint2 v2 = hp[(size_t)e2.x * 32 + lane];
        uint2 v3 = hp[(size_t)e3.x * 32 + lane];
        h4_fma(__int_as_float(e0.y), v0, ax, ay, az, aw);
        h4_fma(__int_as_float(e1.y), v1, ax, ay, az, aw);
        h4_fma(__int_as_float(e2.y), v2, ax, ay, az, aw);
        h4_fma(__int_as_float(e3.y), v3, ax, ay, az, aw);
    }
    for (; t < end; t++) {
        int2 e = g_edge[t];
        h4_fma(__int_as_float(e.y), hp[(size_t)e.x * 32 + lane], ax, ay, az, aw);
    }
    float4 b = ((const float4*)bias)[lane];
    ax = fmaxf(ax + b.x, 0.f); ay = fmaxf(ay + b.y, 0.f);
    az = fmaxf(az + b.z, 0.f); aw = fmaxf(aw + b.w, 0.f);

    float4 w3v = __ldg(&((const float4*)W3)[lane]);
    float s = ax * w3v.x + ay * w3v.y + az * w3v.z + aw * w3v.w;
#pragma unroll
    for (int off = 16; off; off >>= 1) s += __shfl_xor_sync(0xFFFFFFFFu, s, off);
    if (lane == 0) h3[gw] = s;
}

// Layer-3 scalar aggregation: out = relu(agg(h3) + b3)
__global__ void k_agg3(const float* __restrict__ h3, const float* __restrict__ b3,
                       float* __restrict__ out, int n) {
    int i = blockIdx.x * blockDim.x + threadIdx.x;
    if (i >= n) return;
    float dis = g_dis[i];
    float acc = dis * dis * h3[i];
    int beg = g_rowptr[i], end = g_rowptr[i + 1];
    for (int t = beg; t < end; t++) {
        int2 e = g_edge[t];
        acc = fmaf(__int_as_float(e.y), h3[e.x], acc);
    }
    acc += b3[0];
    out[i] = fmaxf(acc, 0.f);
}

// ---------------------------------------------------------------------------
// Launch
// ---------------------------------------------------------------------------

static inline int cdiv(int a, int b) { return (a + b - 1) / b; }

extern "C" void kernel_launch(void* const* d_in, const int* in_sizes, int n_in,
                              void* d_out, int out_size) {
    const float* x  = (const float*)d_in[0];
    const int*   ei = (const int*)d_in[1];
    const float* ew = (const float*)d_in[2];
    const float* W1 = (const float*)d_in[3];
    const float* b1 = (const float*)d_in[4];
    const float* W2 = (const float*)d_in[5];
    const float* b2 = (const float*)d_in[6];
    const float* W3 = (const float*)d_in[7];
    const float* b3 = (const float*)d_in[8];
    float* out = (float*)d_out;

    int n = in_sizes[0] / D;
    int e = in_sizes[1] / 2;
    const int* src = ei;
    const int* dst = ei + e;

    __half *hbuf, *h2buf;
    float *abuf, *h3buf, *degaddr;
    int* cntaddr;
    cudaGetSymbolAddress((void**)&hbuf, g_h);
    cudaGetSymbolAddress((void**)&h2buf, g_h2);
    cudaGetSymbolAddress((void**)&abuf, g_a);
    cudaGetSymbolAddress((void**)&h3buf, g_h3);
    cudaGetSymbolAddress((void**)&degaddr, g_deg);
    cudaGetSymbolAddress((void**)&cntaddr, g_cnt);

    // One-time stream/event creation (host-side resources only; no device mem).
    static cudaStream_t s_side = nullptr;
    static cudaEvent_t ev_fork = nullptr, ev_join = nullptr, ev_a = nullptr, ev_b = nullptr;
    static int init_tried = 0;
    if (!init_tried) {
        init_tried = 1;
        if (cudaStreamCreateWithFlags(&s_side, cudaStreamNonBlocking) != cudaSuccess) s_side = nullptr;
        if (s_side) {
            if (cudaEventCreateWithFlags(&ev_fork, cudaEventDisableTiming) != cudaSuccess ||
                cudaEventCreateWithFlags(&ev_join, cudaEventDisableTiming) != cudaSuccess ||
                cudaEventCreateWithFlags(&ev_a, cudaEventDisableTiming) != cudaSuccess ||
                cudaEventCreateWithFlags(&ev_b, cudaEventDisableTiming) != cudaSuccess) {
                s_side = nullptr;   // fall back to serial
            }
        }
    }

    int nb1024 = cdiv(n, 1024);
    int nblk   = cdiv(n, BM);            // GEMM row-blocks (782)
    int blk0   = nblk / 2;               // first-half row-blocks
    int rows0  = blk0 * BM;              // pipeline split point (50048)

    if (s_side) {
        // --- Fork: CSR build on s_side, GEMM1 on the main (capturing) stream ---
        cudaEventRecord(ev_fork, 0);
        cudaStreamWaitEvent(s_side, ev_fork, 0);

        cudaMemsetAsync(degaddr, 0, (size_t)n * sizeof(float), s_side);
        cudaMemsetAsync(cntaddr, 0, (size_t)n * sizeof(int), s_side);
        k_degcnt <<<cdiv(e, 256), 256, 0, s_side>>>(dst, ew, e);
        k_scan1  <<<nb1024, 1024, 0, s_side>>>(n);        // also g_dis=rsqrt(deg+1)
        k_scan2  <<<1, 32, 0, s_side>>>(nb1024);
        k_scan3  <<<cdiv(n, 256), 256, 0, s_side>>>(n, e);
        k_scatter<<<cdiv(e, 256), 256, 0, s_side>>>(src, dst, ew, e);
        cudaEventRecord(ev_join, s_side);

        k_gemm<<<nblk, 256>>>(x, W1, hbuf, n, 1, 0);      // overlaps CSR build
        cudaStreamWaitEvent(0, ev_join, 0);               // agg needs CSR + GEMM1

        // --- Layer 1 agg, chunked; half B (reads g_h) overlaps GEMM2 half A
        //     (writes g_h2) — disjoint buffers, no race ---
        k_agg_relu<<<cdiv(rows0 * 32, 256), 256>>>(hbuf, b1, abuf, 0, rows0);
        cudaEventRecord(ev_a, 0);
        cudaStreamWaitEvent(s_side, ev_a, 0);
        k_agg_relu<<<cdiv((n - rows0) * 32, 256), 256, 0, s_side>>>(hbuf, b1, abuf, rows0, n);
        cudaEventRecord(ev_b, s_side);

        k_gemm<<<blk0, 256>>>(abuf, W2, h2buf, n, 0, 0);  // concurrent with agg half B
        cudaStreamWaitEvent(0, ev_b, 0);
        k_gemm<<<nblk - blk0, 256>>>(abuf, W2, h2buf, n, 0, rows0);
    } else {
        // Serial fallback (known-good ordering).
        cudaMemsetAsync(degaddr, 0, (size_t)n * sizeof(float), 0);
        cudaMemsetAsync(cntaddr, 0, (size_t)n * sizeof(int), 0);
        k_degcnt <<<cdiv(e, 256), 256>>>(dst, ew, e);
        k_scan1  <<<nb1024, 1024>>>(n);
        k_scan2  <<<1, 32>>>(nb1024);
        k_scan3  <<<cdiv(n, 256), 256>>>(n, e);
        k_scatter<<<cdiv(e, 256), 256>>>(src, dst, ew, e);
        k_gemm<<<nblk, 256>>>(x, W1, hbuf, n, 1, 0);
        k_agg_relu<<<cdiv(n * 32, 256), 256>>>(hbuf, b1, abuf, 0, n);
        k_gemm<<<nblk, 256>>>(abuf, W2, h2buf, n, 0, 0);
    }

    // --- Layer 2 aggregation fused with final GEMV (reads g_h2) ---
    k_agg_relu_gemv<<<cdiv(n * 32, 256), 256>>>(h2buf, b2, W3, h3buf, n);

    // --- Layer 3 (scalar) ---
    k_agg3<<<cdiv(n, 256), 256>>>(h3buf, b3, out, n);
}